// round 16
// baseline (speedup 1.0000x reference)
#include <cuda_runtime.h>
#include <cstdint>

#define DEV_INLINE __device__ __forceinline__

// ---------------------------------------------------------------------------
// tf32 helpers
// ---------------------------------------------------------------------------
DEV_INLINE float to_tf32(float x) {
    uint32_t u;
    asm("cvt.rna.tf32.f32 %0, %1;" : "=r"(u) : "f"(x));
    return __uint_as_float(u);
}

DEV_INLINE void cp_async16(void* smp, const void* gmp) {
    uint32_t sa = (uint32_t)__cvta_generic_to_shared(smp);
    asm volatile("cp.async.cg.shared.global [%0], [%1], 16;\n" :: "r"(sa), "l"(gmp));
}
DEV_INLINE void cp_commit() { asm volatile("cp.async.commit_group;\n" ::: "memory"); }
DEV_INLINE void cp_wait1()  { asm volatile("cp.async.wait_group 1;\n" ::: "memory"); }

// D = A(tf32) * B(tf32) + C, m16n8k8, fp32 accumulate
DEV_INLINE void mma_tf32(float* c, const float* a, const float* b) {
    asm volatile(
        "mma.sync.aligned.m16n8k8.row.col.f32.tf32.tf32.f32 "
        "{%0,%1,%2,%3}, {%4,%5,%6,%7}, {%8,%9}, {%0,%1,%2,%3};\n"
        : "+f"(c[0]), "+f"(c[1]), "+f"(c[2]), "+f"(c[3])
        : "r"(__float_as_uint(a[0])), "r"(__float_as_uint(a[1])),
          "r"(__float_as_uint(a[2])), "r"(__float_as_uint(a[3])),
          "r"(__float_as_uint(b[0])), "r"(__float_as_uint(b[1])));
}

// ---------------------------------------------------------------------------
// Problem constants & scratch (all dims are multiples of the tile sizes,
// so the GEMM kernel needs no bounds checks)
// ---------------------------------------------------------------------------
constexpr int CB = 8;        // batch
constexpr int CS = 2048;     // S1 == S2
constexpr int CD = 512;      // model dim
constexpr int CMT = CB * CS; // 16384 total rows

__device__ float g_x1t[(size_t)CMT * CD];   // tf32-rounded x1
__device__ float g_x2t[(size_t)CMT * CD];   // tf32-rounded x2
__device__ float g_wq[CD * CD];
__device__ float g_wk[CD * CD];
__device__ float g_wv[CD * CD];
__device__ float g_q[(size_t)CMT * CD];
__device__ float g_k[(size_t)CMT * CD];
__device__ float g_v[(size_t)CMT * CD];
__device__ float g_s[(size_t)CB * CS * CS]; // scores / attn probs (128 MB)

// ---------------------------------------------------------------------------
// Elementwise round-to-tf32 prepass
// ---------------------------------------------------------------------------
__global__ void round_tf32_kernel(float* __restrict__ dst, const float* __restrict__ src, int n4) {
    int i = blockIdx.x * blockDim.x + threadIdx.x;
    if (i < n4) {
        float4 v = reinterpret_cast<const float4*>(src)[i];
        v.x = to_tf32(v.x); v.y = to_tf32(v.y);
        v.z = to_tf32(v.z); v.w = to_tf32(v.w);
        reinterpret_cast<float4*>(dst)[i] = v;
    }
}

// ---------------------------------------------------------------------------
// Generic tf32 tensor-core GEMM
//   C[M,N] = scale * (A[M,K] @ op(B)) + bias
//   BLAYOUT 0: B is [N,K] row-major (K-contiguous, "NT": weights / K for QK^T)
//   BLAYOUT 1: B is [K,N] row-major (N-contiguous, "NN": V for P@V)
//   ROUND_OUT: round result to tf32 on store (for tensors consumed by later MMAs)
// CTA: 256 threads, tile 128x128, BK=32, cp.async double-buffered.
// All of M, N are multiples of 128 and K of 32.
// ---------------------------------------------------------------------------
constexpr int BM = 128, BN = 128, BK = 32;
constexpr int AST    = BK + 4;        // A smem row stride (36) -> conflict-free frags
constexpr int ASZ    = BM * AST;      // floats per A stage
constexpr int BST_NT = BK + 4;        // 36
constexpr int BST_NN = BN + 8;        // 136 -> conflict-free b-frag reads
constexpr int BSZ_NT = BN * BST_NT;
constexpr int BSZ_NN = BK * BST_NN;
constexpr int SMEM_NT = (2 * ASZ + 2 * BSZ_NT) * 4;  // 73728 B
constexpr int SMEM_NN = (2 * ASZ + 2 * BSZ_NN) * 4;  // 71680 B

template <int BLAYOUT, bool ROUND_OUT>
__global__ void __launch_bounds__(256, 2)
gemm_tf32(const float* __restrict__ Ag, const float* __restrict__ Bg, float* __restrict__ Cg,
          int M, int N, int K,
          long long sAb, long long sBb, long long sCb,
          const float* __restrict__ bias, float scale)
{
    extern __shared__ float smbase[];
    constexpr int BSZ = (BLAYOUT == 0) ? BSZ_NT : BSZ_NN;
    float* As = smbase;
    float* Bs = smbase + 2 * ASZ;

    const int tid  = threadIdx.x;
    const int lane = tid & 31;
    const int warp = tid >> 5;
    const int g    = lane >> 2;   // groupID (0..7)
    const int tg   = lane & 3;    // threadID_in_group (0..3)
    const int m0   = (warp >> 1) * 32;  // warp M offset (4 warps in M)
    const int n0   = (warp & 1) * 64;   // warp N offset (2 warps in N)

    const float* A = Ag + (long long)blockIdx.z * sAb;
    const float* B = Bg + (long long)blockIdx.z * sBb;
    float*       C = Cg + (long long)blockIdx.z * sCb;

    const int brow = blockIdx.y * BM;
    const int bcol = blockIdx.x * BN;

    float acc[2][8][4];
    #pragma unroll
    for (int i = 0; i < 2; i++)
        #pragma unroll
        for (int j = 0; j < 8; j++)
            #pragma unroll
            for (int c = 0; c < 4; c++) acc[i][j][c] = 0.f;

    // global->smem load geometry (float4 per thread per pass, 4 passes)
    const int ar = tid >> 3;          // 0..31 (row within 32-row slab)
    const int ac = (tid & 7) << 2;    // 0..28 (k columns, NT)
    const int br = tid >> 5;          // 0..7  (k row, NN)
    const int bc = (tid & 31) << 2;   // 0..124 (n columns, NN)

    const float* Agl    = A + (long long)(brow + ar) * K + ac;
    const float* Bgl_nt = B + (long long)(bcol + ar) * K + ac;
    const float* Bgl_nn = B + (long long)br * N + bcol + bc;

    const int nkt = K / BK;

    auto issue_tile = [&](int kt, int stage) {
        const int k0 = kt * BK;
        #pragma unroll
        for (int p = 0; p < 4; p++)
            cp_async16(&As[stage * ASZ + (ar + p * 32) * AST + ac],
                       Agl + (long long)(p * 32) * K + k0);
        if (BLAYOUT == 0) {
            #pragma unroll
            for (int p = 0; p < 4; p++)
                cp_async16(&Bs[stage * BSZ + (ar + p * 32) * BST_NT + ac],
                           Bgl_nt + (long long)(p * 32) * K + k0);
        } else {
            #pragma unroll
            for (int p = 0; p < 4; p++)
                cp_async16(&Bs[stage * BSZ + (br + p * 8) * BST_NN + bc],
                           Bgl_nn + (long long)(k0 + p * 8) * N);
        }
    };

    issue_tile(0, 0);
    cp_commit();

    for (int kt = 0; kt < nkt; ++kt) {
        const int buf = kt & 1;
        if (kt + 1 < nkt) issue_tile(kt + 1, buf ^ 1);
        cp_commit();
        cp_wait1();           // tile kt landed
        __syncthreads();

        const float* Ab = &As[buf * ASZ];
        const float* Bb = &Bs[buf * BSZ];
        #pragma unroll
        for (int kk = 0; kk < BK / 8; ++kk) {
            const int kb = kk * 8;
            float af[2][4];
            #pragma unroll
            for (int mt = 0; mt < 2; ++mt) {
                const int m = m0 + mt * 16 + g;
                af[mt][0] = Ab[(m    ) * AST + kb + tg];
                af[mt][1] = Ab[(m + 8) * AST + kb + tg];
                af[mt][2] = Ab[(m    ) * AST + kb + tg + 4];
                af[mt][3] = Ab[(m + 8) * AST + kb + tg + 4];
            }
            float bf[8][2];
            #pragma unroll
            for (int nt = 0; nt < 8; ++nt) {
                const int n = n0 + nt * 8 + g;
                if (BLAYOUT == 0) {
                    bf[nt][0] = Bb[n * BST_NT + kb + tg];
                    bf[nt][1] = Bb[n * BST_NT + kb + tg + 4];
                } else {
                    bf[nt][0] = Bb[(kb + tg    ) * BST_NN + n];
                    bf[nt][1] = Bb[(kb + tg + 4) * BST_NN + n];
                }
            }
            #pragma unroll
            for (int mt = 0; mt < 2; ++mt)
                #pragma unroll
                for (int nt = 0; nt < 8; ++nt)
                    mma_tf32(acc[mt][nt], af[mt], bf[nt]);
        }
        __syncthreads();  // protect next iteration's cp.async writes
    }

    // epilogue: scale, bias, optional tf32 rounding, float2 stores
    #pragma unroll
    for (int mt = 0; mt < 2; ++mt) {
        const int r = brow + m0 + mt * 16 + g;
        #pragma unroll
        for (int nt = 0; nt < 8; ++nt) {
            const int n = bcol + n0 + nt * 8 + tg * 2;
            float b0 = 0.f, b1 = 0.f;
            if (bias) { b0 = bias[n]; b1 = bias[n + 1]; }
            float o00 = acc[mt][nt][0] * scale + b0;
            float o01 = acc[mt][nt][1] * scale + b1;
            float o10 = acc[mt][nt][2] * scale + b0;
            float o11 = acc[mt][nt][3] * scale + b1;
            if (ROUND_OUT) {
                o00 = to_tf32(o00); o01 = to_tf32(o01);
                o10 = to_tf32(o10); o11 = to_tf32(o11);
            }
            *reinterpret_cast<float2*>(C + (long long)r * N + n)       = make_float2(o00, o01);
            *reinterpret_cast<float2*>(C + (long long)(r + 8) * N + n) = make_float2(o10, o11);
        }
    }
}

// ---------------------------------------------------------------------------
// Row softmax over 2048 columns, one 256-thread CTA per row.
// Writes tf32-rounded probabilities (consumed by the PV tensor-core GEMM).
// ---------------------------------------------------------------------------
__global__ void softmax_rows_2048(float* __restrict__ Sp) {
    const long long row = blockIdx.x;
    float* p = Sp + row * 2048ll;
    const int tid = threadIdx.x;

    float4 a = *reinterpret_cast<const float4*>(p + tid * 4);
    float4 b = *reinterpret_cast<const float4*>(p + 1024 + tid * 4);

    float m = fmaxf(fmaxf(fmaxf(a.x, a.y), fmaxf(a.z, a.w)),
                    fmaxf(fmaxf(b.x, b.y), fmaxf(b.z, b.w)));
    #pragma unroll
    for (int o = 16; o > 0; o >>= 1) m = fmaxf(m, __shfl_xor_sync(0xffffffffu, m, o));

    __shared__ float redm[8], reds[8];
    const int warp = tid >> 5, lane = tid & 31;
    if (lane == 0) redm[warp] = m;
    __syncthreads();
    float mm = redm[0];
    #pragma unroll
    for (int i = 1; i < 8; i++) mm = fmaxf(mm, redm[i]);

    a.x = __expf(a.x - mm); a.y = __expf(a.y - mm);
    a.z = __expf(a.z - mm); a.w = __expf(a.w - mm);
    b.x = __expf(b.x - mm); b.y = __expf(b.y - mm);
    b.z = __expf(b.z - mm); b.w = __expf(b.w - mm);

    float s = a.x + a.y + a.z + a.w + b.x + b.y + b.z + b.w;
    #pragma unroll
    for (int o = 16; o > 0; o >>= 1) s += __shfl_xor_sync(0xffffffffu, s, o);
    if (lane == 0) reds[warp] = s;
    __syncthreads();
    float ss = reds[0];
    #pragma unroll
    for (int i = 1; i < 8; i++) ss += reds[i];

    const float inv = 1.0f / ss;
    a.x = to_tf32(a.x * inv); a.y = to_tf32(a.y * inv);
    a.z = to_tf32(a.z * inv); a.w = to_tf32(a.w * inv);
    b.x = to_tf32(b.x * inv); b.y = to_tf32(b.y * inv);
    b.z = to_tf32(b.z * inv); b.w = to_tf32(b.w * inv);

    *reinterpret_cast<float4*>(p + tid * 4) = a;
    *reinterpret_cast<float4*>(p + 1024 + tid * 4) = b;
}

// ---------------------------------------------------------------------------
// kernel_launch: prepass rounds inputs to tf32; then
//   Q/K/V projections (NT) -> scores QK^T (NT, batched) -> softmax -> PV (NN)
// ---------------------------------------------------------------------------
extern "C" void kernel_launch(void* const* d_in, const int* in_sizes, int n_in,
                              void* d_out, int out_size)
{
    (void)in_sizes; (void)n_in; (void)out_size;
    const float* x1 = (const float*)d_in[0];
    const float* x2 = (const float*)d_in[1];
    const float* Wq = (const float*)d_in[2];
    const float* bq = (const float*)d_in[3];
    const float* Wk = (const float*)d_in[4];
    const float* bk = (const float*)d_in[5];
    const float* Wv = (const float*)d_in[6];
    const float* bv = (const float*)d_in[7];
    float* out = (float*)d_out;

    float *x1t, *x2t, *wq, *wk, *wv, *q, *k, *v, *s;
    cudaGetSymbolAddress((void**)&x1t, g_x1t);
    cudaGetSymbolAddress((void**)&x2t, g_x2t);
    cudaGetSymbolAddress((void**)&wq,  g_wq);
    cudaGetSymbolAddress((void**)&wk,  g_wk);
    cudaGetSymbolAddress((void**)&wv,  g_wv);
    cudaGetSymbolAddress((void**)&q,   g_q);
    cudaGetSymbolAddress((void**)&k,   g_k);
    cudaGetSymbolAddress((void**)&v,   g_v);
    cudaGetSymbolAddress((void**)&s,   g_s);

    cudaFuncSetAttribute(gemm_tf32<0, true>,  cudaFuncAttributeMaxDynamicSharedMemorySize, SMEM_NT);
    cudaFuncSetAttribute(gemm_tf32<0, false>, cudaFuncAttributeMaxDynamicSharedMemorySize, SMEM_NT);
    cudaFuncSetAttribute(gemm_tf32<1, false>, cudaFuncAttributeMaxDynamicSharedMemorySize, SMEM_NN);

    dim3 blk(256);

    // 1. round inputs/weights to tf32 (round-to-nearest; truncation would bias dots ~1e-3)
    {
        int n4 = CMT * CD / 4;
        round_tf32_kernel<<<(n4 + 255) / 256, 256>>>(x1t, x1, n4);
        round_tf32_kernel<<<(n4 + 255) / 256, 256>>>(x2t, x2, n4);
        int w4 = CD * CD / 4;
        round_tf32_kernel<<<(w4 + 255) / 256, 256>>>(wq, Wq, w4);
        round_tf32_kernel<<<(w4 + 255) / 256, 256>>>(wk, Wk, w4);
        round_tf32_kernel<<<(w4 + 255) / 256, 256>>>(wv, Wv, w4);
    }

    // 2. projections: [16384,512] = x @ W^T + b   (outputs tf32-rounded)
    {
        dim3 grid(CD / BN, CMT / BM, 1);
        gemm_tf32<0, true><<<grid, blk, SMEM_NT>>>(x1t, wq, q, CMT, CD, CD, 0, 0, 0, bq, 1.f);
        gemm_tf32<0, true><<<grid, blk, SMEM_NT>>>(x2t, wk, k, CMT, CD, CD, 0, 0, 0, bk, 1.f);
        gemm_tf32<0, true><<<grid, blk, SMEM_NT>>>(x2t, wv, v, CMT, CD, CD, 0, 0, 0, bv, 1.f);
    }

    // 3. scores: S[b] = Q[b] @ K[b]^T / D   (batched NT)
    {
        dim3 grid(CS / BN, CS / BM, CB);
        gemm_tf32<0, false><<<grid, blk, SMEM_NT>>>(
            q, k, s, CS, CS, CD,
            (long long)CS * CD, (long long)CS * CD, (long long)CS * CS,
            nullptr, 1.f / (float)CD);
    }

    // 4. softmax rows (writes tf32-rounded P in place)
    softmax_rows_2048<<<CMT, 256>>>(s);

    // 5. out[b] = P[b] @ V[b]   (batched NN, fp32 out)
    {
        dim3 grid(CD / BN, CS / BM, CB);
        gemm_tf32<1, false><<<grid, blk, SMEM_NN>>>(
            s, v, out, CS, CD, CS,
            (long long)CS * CS, (long long)CS * CD, (long long)CS * CD,
            nullptr, 1.f);
    }
}